// round 6
// baseline (speedup 1.0000x reference)
#include <cuda_runtime.h>
#include <cuda_bf16.h>
#include <stdint.h>

// ---------------- problem dims ----------------
#define BATCH 8
#define CIN   2
#define HH    64
#define WW    64
#define TT    200
#define NCH   7      // ceil(200/32) chunks of 32 timesteps (tail garbage is causal-safe)
#define C1    8
#define C2    8
#define NTAP1 (CIN * 25)   // 50
#define NTAP2 (C1 * 9)     // 72

// fp32 correctly-rounded decay constants
#define D1 0.36787944117144233f   // exp(-1)    : tau=1 (psp1, ref1)
#define D2 0.60653065971263342f   // exp(-1/2)  : tau=2 (psp2, ref2)
#define D3 0.77880078307140487f   // exp(-1/4)  : tau=4 (psp3, ref3)

// ---------------- bit-packed intermediates ----------------
// layout: [b][chunk][c][h][w], one uint32 = 32 consecutive timesteps
__device__ uint32_t g_xbits[BATCH * NCH * CIN * HH * WW];  // 1.75 MB
__device__ uint32_t g_s1  [BATCH * NCH * C1  * HH * WW];   // 7 MB
__device__ uint32_t g_s2  [BATCH * NCH * C2  * HH * WW];   // 7 MB

// one test gates 4 packed f32x2 adds (8 fp32 accumulators, oc-paired).
// per-lane IEEE fp32 add.rn -> bit-exact vs scalar FADD in same order.
__device__ __forceinline__ void padd4x2(unsigned long long& a0, unsigned long long& a1,
                                        unsigned long long& a2, unsigned long long& a3,
                                        unsigned int maskres,
                                        unsigned long long w0, unsigned long long w1,
                                        unsigned long long w2, unsigned long long w3) {
    asm volatile("{\n\t"
        ".reg .pred p;\n\t"
        "setp.ne.u32 p, %4, 0;\n\t"
        "@p add.rn.f32x2 %0, %0, %5;\n\t"
        "@p add.rn.f32x2 %1, %1, %6;\n\t"
        "@p add.rn.f32x2 %2, %2, %7;\n\t"
        "@p add.rn.f32x2 %3, %3, %8;\n\t"
        "}"
        : "+l"(a0), "+l"(a1), "+l"(a2), "+l"(a3)
        : "r"(maskres), "l"(w0), "l"(w1), "l"(w2), "l"(w3));
}
// one test gates 1 packed f32x2 add (2 fp32 accumulators)
__device__ __forceinline__ void padd1x2(unsigned long long& a0, unsigned int maskres,
                                        unsigned long long w0) {
    asm volatile("{\n\t"
        ".reg .pred p;\n\t"
        "setp.ne.u32 p, %1, 0;\n\t"
        "@p add.rn.f32x2 %0, %0, %2;\n\t"
        "}"
        : "+l"(a0) : "r"(maskres), "l"(w0));
}

__device__ __forceinline__ unsigned long long packf2(float lo, float hi) {
    return (unsigned long long)__float_as_uint(lo) |
           ((unsigned long long)__float_as_uint(hi) << 32);
}

// =====================================================================
// K0: binarize + time-transpose input [b,c,h,w,t] -> bitmasks
// =====================================================================
__global__ void k_binarize(const float* __restrict__ x) {
    int tid = blockIdx.x * blockDim.x + threadIdx.x;
    if (tid >= BATCH * CIN * HH * WW * NCH) return;
    int k   = tid % NCH;
    int pix = tid / NCH;
    int w = pix % WW; int t1 = pix / WW;
    int h = t1 % HH;  t1 /= HH;
    int c = t1 % CIN; int b = t1 / CIN;
    const float* p = x + (size_t)pix * TT + k * 32;
    int n = min(32, TT - k * 32);
    uint32_t bits = 0;
    for (int i = 0; i < n; i++) bits |= (p[i] > 0.5f) ? (1u << i) : 0u;
    g_xbits[(((b * NCH + k) * CIN + c) * HH + h) * WW + w] = bits;
}

// =====================================================================
// K1: layer 1.  u = IIR_1(conv5x5(xbits)); spike(th=30, dref=D1)
// thread = (b,h,w), all 8 oc; oc paired into 4 f32x2 accumulators.
// per tap-bit: 1 test + 4 @p ADD2 (was 1 test + 8 FADD).
// =====================================================================
__global__ void __launch_bounds__(128) k_layer1(const float* __restrict__ w1) {
    // weight pairs: swP[tap*4 + p] = (w[2p][tap], w[2p+1][tap]) packed
    __shared__ unsigned long long swP[NTAP1 * 4];
    for (int i = threadIdx.x; i < NTAP1 * 4; i += blockDim.x) {
        int p = i & 3, tp = i >> 2;
        swP[i] = packf2(w1[(2 * p) * NTAP1 + tp], w1[(2 * p + 1) * NTAP1 + tp]);
    }
    __syncthreads();

    int tid = blockIdx.x * blockDim.x + threadIdx.x;
    int w = tid % WW; int t1 = tid / WW;
    int h = t1 % HH;  int b = t1 / HH;

    float a[C1], r[C1];
#pragma unroll
    for (int o = 0; o < C1; o++) { a[o] = 0.f; r[o] = 0.f; }

    for (int k = 0; k < NCH; k++) {
        uint32_t bits[NTAP1];
#pragma unroll
        for (int c = 0; c < CIN; c++)
#pragma unroll
            for (int dy = 0; dy < 5; dy++)
#pragma unroll
                for (int dx = 0; dx < 5; dx++) {
                    int hh = h + dy - 2, ww = w + dx - 2;
                    uint32_t v = 0;
                    if (hh >= 0 && hh < HH && ww >= 0 && ww < WW)
                        v = g_xbits[(((b * NCH + k) * CIN + c) * HH + hh) * WW + ww];
                    bits[(c * 5 + dy) * 5 + dx] = v;
                }

        uint32_t sb[C1];
#pragma unroll
        for (int o = 0; o < C1; o++) sb[o] = 0u;

#pragma unroll 1
        for (int jg = 0; jg < 4; jg++) {
            unsigned long long acc[4 * 8];     // [pair][jj]
#pragma unroll
            for (int i = 0; i < 32; i++) acc[i] = 0ull;
#pragma unroll 1
            for (int tp = 0; tp < NTAP1; tp++) {
                uint32_t bw = bits[tp] >> (jg * 8);
                unsigned long long w0 = swP[tp * 4 + 0], w1v = swP[tp * 4 + 1];
                unsigned long long w2v = swP[tp * 4 + 2], w3v = swP[tp * 4 + 3];
#pragma unroll
                for (int jj = 0; jj < 8; jj++)
                    padd4x2(acc[0 * 8 + jj], acc[1 * 8 + jj], acc[2 * 8 + jj], acc[3 * 8 + jj],
                            bw & (1u << jj), w0, w1v, w2v, w3v);
            }
#pragma unroll
            for (int jj = 0; jj < 8; jj++) {
                int j = jg * 8 + jj;
#pragma unroll
                for (int pp = 0; pp < 4; pp++) {
                    unsigned long long v = acc[pp * 8 + jj];
                    float slo = __uint_as_float((unsigned)(v & 0xffffffffu));
                    float shi = __uint_as_float((unsigned)(v >> 32));
                    int o0 = 2 * pp, o1 = 2 * pp + 1;
                    a[o0] = D1 * a[o0] + slo;
                    float v0 = a[o0] + r[o0];
                    bool h0 = v0 >= 30.0f;
                    sb[o0] |= h0 ? (1u << j) : 0u;
                    r[o0] = D1 * r[o0] - (h0 ? 30.0f : 0.0f);
                    a[o1] = D1 * a[o1] + shi;
                    float v1 = a[o1] + r[o1];
                    bool h1 = v1 >= 30.0f;
                    sb[o1] |= h1 ? (1u << j) : 0u;
                    r[o1] = D1 * r[o1] - (h1 ? 30.0f : 0.0f);
                }
            }
        }
#pragma unroll
        for (int o = 0; o < C1; o++)
            g_s1[(((b * NCH + k) * C1 + o) * HH + h) * WW + w] = sb[o];
    }
}

// =====================================================================
// K2: layer 2.  u = IIR_2(conv3x3(s1bits)); spike(th=50, dref=D2)
// =====================================================================
__global__ void __launch_bounds__(128) k_layer2(const float* __restrict__ w2) {
    __shared__ unsigned long long swP[NTAP2 * 4];
    for (int i = threadIdx.x; i < NTAP2 * 4; i += blockDim.x) {
        int p = i & 3, tp = i >> 2;
        swP[i] = packf2(w2[(2 * p) * NTAP2 + tp], w2[(2 * p + 1) * NTAP2 + tp]);
    }
    __syncthreads();

    int tid = blockIdx.x * blockDim.x + threadIdx.x;
    int w = tid % WW; int t1 = tid / WW;
    int h = t1 % HH;  int b = t1 / HH;

    float a[C2], r[C2];
#pragma unroll
    for (int o = 0; o < C2; o++) { a[o] = 0.f; r[o] = 0.f; }

    for (int k = 0; k < NCH; k++) {
        uint32_t bits[NTAP2];
#pragma unroll
        for (int c = 0; c < C1; c++)
#pragma unroll
            for (int dy = 0; dy < 3; dy++)
#pragma unroll
                for (int dx = 0; dx < 3; dx++) {
                    int hh = h + dy - 1, ww = w + dx - 1;
                    uint32_t v = 0;
                    if (hh >= 0 && hh < HH && ww >= 0 && ww < WW)
                        v = g_s1[(((b * NCH + k) * C1 + c) * HH + hh) * WW + ww];
                    bits[(c * 3 + dy) * 3 + dx] = v;
                }

        uint32_t sb[C2];
#pragma unroll
        for (int o = 0; o < C2; o++) sb[o] = 0u;

#pragma unroll 1
        for (int jg = 0; jg < 4; jg++) {
            unsigned long long acc[4 * 8];
#pragma unroll
            for (int i = 0; i < 32; i++) acc[i] = 0ull;
#pragma unroll 1
            for (int tp = 0; tp < NTAP2; tp++) {
                uint32_t bw = bits[tp] >> (jg * 8);
                unsigned long long w0 = swP[tp * 4 + 0], w1v = swP[tp * 4 + 1];
                unsigned long long w2v = swP[tp * 4 + 2], w3v = swP[tp * 4 + 3];
#pragma unroll
                for (int jj = 0; jj < 8; jj++)
                    padd4x2(acc[0 * 8 + jj], acc[1 * 8 + jj], acc[2 * 8 + jj], acc[3 * 8 + jj],
                            bw & (1u << jj), w0, w1v, w2v, w3v);
            }
#pragma unroll
            for (int jj = 0; jj < 8; jj++) {
                int j = jg * 8 + jj;
#pragma unroll
                for (int pp = 0; pp < 4; pp++) {
                    unsigned long long v = acc[pp * 8 + jj];
                    float slo = __uint_as_float((unsigned)(v & 0xffffffffu));
                    float shi = __uint_as_float((unsigned)(v >> 32));
                    int o0 = 2 * pp, o1 = 2 * pp + 1;
                    a[o0] = D2 * a[o0] + slo;
                    float v0 = a[o0] + r[o0];
                    bool h0 = v0 >= 50.0f;
                    sb[o0] |= h0 ? (1u << j) : 0u;
                    r[o0] = D2 * r[o0] - (h0 ? 50.0f : 0.0f);
                    a[o1] = D2 * a[o1] + shi;
                    float v1 = a[o1] + r[o1];
                    bool h1 = v1 >= 50.0f;
                    sb[o1] |= h1 ? (1u << j) : 0u;
                    r[o1] = D2 * r[o1] - (h1 ? 50.0f : 0.0f);
                }
            }
        }
#pragma unroll
        for (int o = 0; o < C2; o++)
            g_s2[(((b * NCH + k) * C2 + o) * HH + h) * WW + w] = sb[o];
    }
}

// =====================================================================
// K3: layer 3.  u3 = IIR_4(convT2x2(s2bits)) + IIR_1(bilinear2x(xbits))
//               spike(th=100, dref=D3)
// oc paired in f32x2 for the convT taps; nibble->float4 LUT stores.
// =====================================================================
__global__ void __launch_bounds__(128) k_layer3(const float* __restrict__ wup,
                                                float* __restrict__ out) {
    __shared__ float swu[64];
    __shared__ float4 lutf[16];
    if (threadIdx.x < 64) swu[threadIdx.x] = wup[threadIdx.x];
    if (threadIdx.x < 16) {
        int n = threadIdx.x;
        lutf[n] = make_float4((n & 1) ? 1.f : 0.f, (n & 2) ? 1.f : 0.f,
                              (n & 4) ? 1.f : 0.f, (n & 8) ? 1.f : 0.f);
    }
    __syncthreads();

    int tid = blockIdx.x * blockDim.x + threadIdx.x;
    int wo = tid & 127; int t1 = tid >> 7;
    int ho = t1 & 127;  int b  = t1 >> 7;
    int hi = ho >> 1, wi = wo >> 1;
    int pa = ho & 1,  pb = wo & 1;

    int r0, r1, c0, c1; float wr0, wr1, wc0, wc1;
    if (!pa) { r0 = (hi > 0) ? hi - 1 : 0;  r1 = hi; wr0 = 0.25f; wr1 = 0.75f; }
    else     { r0 = hi; r1 = (hi < 63) ? hi + 1 : 63; wr0 = 0.75f; wr1 = 0.25f; }
    if (!pb) { c0 = (wi > 0) ? wi - 1 : 0;  c1 = wi; wc0 = 0.25f; wc1 = 0.75f; }
    else     { c0 = wi; c1 = (wi < 63) ? wi + 1 : 63; wc0 = 0.75f; wc1 = 0.25f; }
    float tw[4];
    tw[0] = wr0 * wc0; tw[1] = wr0 * wc1; tw[2] = wr1 * wc0; tw[3] = wr1 * wc1;

    // convT weight pairs (o=0, o=1) per tap c, fixed (pa,pb) per thread
    unsigned long long wAp[C2];
#pragma unroll
    for (int c = 0; c < C2; c++)
        wAp[c] = packf2(swu[((0 * 8 + c) * 2 + (1 - pa)) * 2 + (1 - pb)],
                        swu[((1 * 8 + c) * 2 + (1 - pa)) * 2 + (1 - pb)]);

    float av[2], pv[2], rv[2];
#pragma unroll
    for (int o = 0; o < 2; o++) { av[o] = 0.f; pv[o] = 0.f; rv[o] = 0.f; }

    for (int k = 0; k < NCH; k++) {
        uint32_t s2b[C2];
#pragma unroll
        for (int c = 0; c < C2; c++)
            s2b[c] = g_s2[(((b * NCH + k) * C2 + c) * HH + hi) * WW + wi];
        uint32_t xb[2][4];
#pragma unroll
        for (int o = 0; o < 2; o++) {
            const uint32_t* xp = g_xbits + (size_t)(((b * NCH + k) * CIN) + o) * HH * WW;
            xb[o][0] = xp[r0 * WW + c0]; xb[o][1] = xp[r0 * WW + c1];
            xb[o][2] = xp[r1 * WW + c0]; xb[o][3] = xp[r1 * WW + c1];
        }

        uint32_t sb[2] = {0u, 0u};
#pragma unroll 1
        for (int jg = 0; jg < 4; jg++) {
            unsigned long long accA[8];
#pragma unroll
            for (int i = 0; i < 8; i++) accA[i] = 0ull;
#pragma unroll
            for (int c = 0; c < C2; c++) {
                uint32_t bw = s2b[c] >> (jg * 8);
                unsigned long long wp = wAp[c];
#pragma unroll
                for (int jj = 0; jj < 8; jj++)
                    padd1x2(accA[jj], bw & (1u << jj), wp);
            }
            float sx[2][8];
#pragma unroll
            for (int o = 0; o < 2; o++)
#pragma unroll
                for (int jj = 0; jj < 8; jj++) sx[o][jj] = 0.f;
#pragma unroll
            for (int o = 0; o < 2; o++)
#pragma unroll
                for (int tp = 0; tp < 4; tp++) {
                    uint32_t bw = xb[o][tp] >> (jg * 8);
                    float twv = tw[tp];
#pragma unroll
                    for (int jj = 0; jj < 8; jj++)
                        if (bw & (1u << jj)) sx[o][jj] += twv;
                }
#pragma unroll
            for (int jj = 0; jj < 8; jj++) {
                int j = jg * 8 + jj;
                unsigned long long v = accA[jj];
                float sa[2];
                sa[0] = __uint_as_float((unsigned)(v & 0xffffffffu));
                sa[1] = __uint_as_float((unsigned)(v >> 32));
#pragma unroll
                for (int o = 0; o < 2; o++) {
                    av[o] = D3 * av[o] + sa[o];
                    pv[o] = D1 * pv[o] + sx[o][jj];
                    float u = av[o] + pv[o] + rv[o];
                    bool hd = u >= 100.0f;
                    sb[o] |= hd ? (1u << j) : 0u;
                    rv[o] = D3 * rv[o] - (hd ? 100.0f : 0.0f);
                }
            }
        }

        // nibble-LUT float4 stores: each thread writes its own pixel's 32 t's (128B contiguous)
        int n4 = (k == NCH - 1) ? 2 : 8;   // chunk 6: only t=192..199 valid
#pragma unroll
        for (int o = 0; o < 2; o++) {
            size_t pbase = (((size_t)((b * 2 + o) * 128 + ho) * 128 + wo) * TT) + (size_t)k * 32;
            float4* outv = (float4*)(out + pbase);
#pragma unroll
            for (int i = 0; i < 8; i++)
                if (i < n4) outv[i] = lutf[(sb[o] >> (4 * i)) & 15];
        }
    }
}

// =====================================================================
extern "C" void kernel_launch(void* const* d_in, const int* in_sizes, int n_in,
                              void* d_out, int out_size) {
    const float* x   = (const float*)d_in[0];
    const float* w1  = (const float*)d_in[1];
    const float* w2  = (const float*)d_in[2];
    const float* wup = (const float*)d_in[3];
    float* out = (float*)d_out;

    int n0 = BATCH * CIN * HH * WW * NCH;
    k_binarize<<<(n0 + 255) / 256, 256>>>(x);
    k_layer1<<<(BATCH * HH * WW) / 128, 128>>>(w1);     // 256 blocks
    k_layer2<<<(BATCH * HH * WW) / 128, 128>>>(w2);     // 256 blocks
    k_layer3<<<(BATCH * 128 * 128) / 128, 128>>>(wup, out); // 1024 blocks
}

// round 7
// speedup vs baseline: 1.4772x; 1.4772x over previous
#include <cuda_runtime.h>
#include <cuda_bf16.h>
#include <stdint.h>

// ---------------- problem dims ----------------
#define BATCH 8
#define CIN   2
#define HH    64
#define WW    64
#define TT    200
#define NCH   7      // ceil(200/32) chunks of 32 timesteps (tail garbage is causal-safe)
#define C1    8
#define C2    8
#define NTAP1 (CIN * 25)   // 50
#define NTAP2 (C1 * 9)     // 72

// fp32 correctly-rounded decay constants
#define D1 0.36787944117144233f   // exp(-1)    : tau=1 (psp1, ref1)
#define D2 0.60653065971263342f   // exp(-1/2)  : tau=2 (psp2, ref2)
#define D3 0.77880078307140487f   // exp(-1/4)  : tau=4 (psp3, ref3)

// dynamic smem sizes (floats): LUT slices of 256 entries x 8 oc
#define L1_SLICES 6                 // 2 cin x 3 groups of 8 taps (tap 24 handled separately)
#define L2_SLICES 8                 // 8 cin x 1 group of 8 taps (tap 8 handled separately)
#define SMEM1_FLOATS (L1_SLICES * 256 * 8 + 16)
#define SMEM2_FLOATS (L2_SLICES * 256 * 8 + 64)

// ---------------- bit-packed intermediates ----------------
__device__ uint32_t g_xbits[BATCH * NCH * CIN * HH * WW];  // 1.75 MB
__device__ uint32_t g_s1  [BATCH * NCH * C1  * HH * WW];   // 7 MB
__device__ uint32_t g_s2  [BATCH * NCH * C2  * HH * WW];   // 7 MB

__device__ __forceinline__ void addf4(float4& a, const float4 b) {
    a.x += b.x; a.y += b.y; a.z += b.z; a.w += b.w;
}

// 8x32 -> per-j byte extraction for one jg (8 timesteps):
// gather byte jg of 8 tap-words, then 8x8 bit transpose.
// result: byte jj = 8 tap-bits at timestep jg*8+jj.
__device__ __forceinline__ unsigned long long t8x8(const uint32_t* w, int jg) {
    uint32_t s = (uint32_t)jg | (((uint32_t)jg + 4) << 4);   // pick byte jg of a, byte jg of b
    uint32_t r01 = __byte_perm(w[0], w[1], s);
    uint32_t r23 = __byte_perm(w[2], w[3], s);
    uint32_t r45 = __byte_perm(w[4], w[5], s);
    uint32_t r67 = __byte_perm(w[6], w[7], s);
    uint32_t lo = __byte_perm(r01, r23, 0x5410);
    uint32_t hi = __byte_perm(r45, r67, 0x5410);
    unsigned long long x = (unsigned long long)lo | ((unsigned long long)hi << 32);
    unsigned long long t;
    t = (x ^ (x >> 7))  & 0x00AA00AA00AA00AAull; x = x ^ t ^ (t << 7);
    t = (x ^ (x >> 14)) & 0x0000CCCC0000CCCCull; x = x ^ t ^ (t << 14);
    t = (x ^ (x >> 28)) & 0x00000000F0F0F0F0ull; x = x ^ t ^ (t << 28);
    return x;
}

// =====================================================================
// K0: binarize + time-transpose input [b,c,h,w,t] -> bitmasks
// =====================================================================
__global__ void k_binarize(const float* __restrict__ x) {
    int tid = blockIdx.x * blockDim.x + threadIdx.x;
    if (tid >= BATCH * CIN * HH * WW * NCH) return;
    int k   = tid % NCH;
    int pix = tid / NCH;
    int w = pix % WW; int t1 = pix / WW;
    int h = t1 % HH;  t1 /= HH;
    int c = t1 % CIN; int b = t1 / CIN;
    const float* p = x + (size_t)pix * TT + k * 32;
    int n = min(32, TT - k * 32);
    uint32_t bits = 0;
    for (int i = 0; i < n; i++) bits |= (p[i] > 0.5f) ? (1u << i) : 0u;
    g_xbits[(((b * NCH + k) * CIN + c) * HH + h) * WW + w] = bits;
}

// =====================================================================
// K1: layer 1.  u = IIR_1(conv5x5(xbits)); spike(th=30, dref=D1)
// subset-sum LUT: per (c, group-of-8-taps): 256 x 8oc partial sums.
// per jj: byte index -> 2 LDS.128 + 8 FADD  (was 8 tests + 64 FADD)
// =====================================================================
__global__ void __launch_bounds__(128) k_layer1(const float* __restrict__ w1) {
    extern __shared__ float dyn[];
    float* lut = dyn;                        // [slice(6)][m(256)][oc(8)]
    float* ex  = dyn + L1_SLICES * 256 * 8;  // [c(2)][oc(8)] tap-24 weights
    {
        int t = threadIdx.x;
        if (t < 48) {
            int c = t / 24, g = (t / 8) % 3, o = t & 7;
            int gi = c * 3 + g;
            float wr[8];
#pragma unroll
            for (int p = 0; p < 8; p++) wr[p] = w1[o * NTAP1 + c * 25 + g * 8 + p];
            lut[(gi * 256 + 0) * 8 + o] = 0.f;
            for (int m = 1; m < 256; m++) {
                int pm = 31 - __clz(m);
                lut[(gi * 256 + m) * 8 + o] =
                    lut[(gi * 256 + (m ^ (1 << pm))) * 8 + o] + wr[pm];
            }
        }
        if (t < 16) {
            int c = t >> 3, o = t & 7;
            ex[c * 8 + o] = w1[o * NTAP1 + c * 25 + 24];
        }
    }
    __syncthreads();
    const float4* lutv = (const float4*)lut;
    const float4* exv  = (const float4*)ex;

    int tid = blockIdx.x * blockDim.x + threadIdx.x;
    int w = tid % WW; int t1 = tid / WW;
    int h = t1 % HH;  int b = t1 / HH;

    float a[C1], r[C1];
#pragma unroll
    for (int o = 0; o < C1; o++) { a[o] = 0.f; r[o] = 0.f; }

    for (int k = 0; k < NCH; k++) {
        uint32_t bits[NTAP1];
#pragma unroll
        for (int c = 0; c < CIN; c++)
#pragma unroll
            for (int dy = 0; dy < 5; dy++)
#pragma unroll
                for (int dx = 0; dx < 5; dx++) {
                    int hh = h + dy - 2, ww = w + dx - 2;
                    uint32_t v = 0;
                    if (hh >= 0 && hh < HH && ww >= 0 && ww < WW)
                        v = g_xbits[(((b * NCH + k) * CIN + c) * HH + hh) * WW + ww];
                    bits[(c * 5 + dy) * 5 + dx] = v;
                }

        uint32_t sb[C1];
#pragma unroll
        for (int o = 0; o < C1; o++) sb[o] = 0u;

#pragma unroll 1
        for (int jg = 0; jg < 4; jg++) {
            float4 sl[8], sh[8];
#pragma unroll
            for (int jj = 0; jj < 8; jj++) {
                sl[jj] = make_float4(0.f, 0.f, 0.f, 0.f);
                sh[jj] = make_float4(0.f, 0.f, 0.f, 0.f);
            }
#pragma unroll 1
            for (int c = 0; c < CIN; c++) {
#pragma unroll
                for (int g = 0; g < 3; g++) {
                    int gi = c * 3 + g;
                    unsigned long long tx = t8x8(bits + c * 25 + g * 8, jg);
#pragma unroll
                    for (int jj = 0; jj < 8; jj++) {
                        int m = (int)(tx >> (8 * jj)) & 0xFF;
                        const float4* e = &lutv[(size_t)((gi << 8) | m) << 1];
                        addf4(sl[jj], e[0]);
                        addf4(sh[jj], e[1]);
                    }
                }
                float4 e0 = exv[c * 2], e1 = exv[c * 2 + 1];
                uint32_t b24 = (bits[c * 25 + 24] >> (jg * 8)) & 0xFF;
#pragma unroll
                for (int jj = 0; jj < 8; jj++)
                    if ((b24 >> jj) & 1u) { addf4(sl[jj], e0); addf4(sh[jj], e1); }
            }
#pragma unroll
            for (int jj = 0; jj < 8; jj++) {
                int j = jg * 8 + jj;
                float su[8] = {sl[jj].x, sl[jj].y, sl[jj].z, sl[jj].w,
                               sh[jj].x, sh[jj].y, sh[jj].z, sh[jj].w};
#pragma unroll
                for (int o = 0; o < C1; o++) {
                    a[o] = D1 * a[o] + su[o];
                    float v = a[o] + r[o];
                    bool hd = v >= 30.0f;
                    sb[o] |= hd ? (1u << j) : 0u;
                    r[o] = D1 * r[o] - (hd ? 30.0f : 0.0f);
                }
            }
        }
#pragma unroll
        for (int o = 0; o < C1; o++)
            g_s1[(((b * NCH + k) * C1 + o) * HH + h) * WW + w] = sb[o];
    }
}

// =====================================================================
// K2: layer 2.  u = IIR_2(conv3x3(s1bits)); spike(th=50, dref=D2)
// 8 channels x (8 taps via LUT + tap8 predicated)
// =====================================================================
__global__ void __launch_bounds__(128) k_layer2(const float* __restrict__ w2) {
    extern __shared__ float dyn[];
    float* lut = dyn;                        // [c(8)][m(256)][oc(8)]
    float* ex  = dyn + L2_SLICES * 256 * 8;  // [c(8)][oc(8)] tap-8 weights
    {
        int t = threadIdx.x;
        if (t < 64) {
            int c = t >> 3, o = t & 7;
            float wr[8];
#pragma unroll
            for (int p = 0; p < 8; p++) wr[p] = w2[o * NTAP2 + c * 9 + p];
            ex[c * 8 + o] = w2[o * NTAP2 + c * 9 + 8];
            lut[(c * 256 + 0) * 8 + o] = 0.f;
            for (int m = 1; m < 256; m++) {
                int pm = 31 - __clz(m);
                lut[(c * 256 + m) * 8 + o] =
                    lut[(c * 256 + (m ^ (1 << pm))) * 8 + o] + wr[pm];
            }
        }
    }
    __syncthreads();
    const float4* lutv = (const float4*)lut;
    const float4* exv  = (const float4*)ex;

    int tid = blockIdx.x * blockDim.x + threadIdx.x;
    int w = tid % WW; int t1 = tid / WW;
    int h = t1 % HH;  int b = t1 / HH;

    float a[C2], r[C2];
#pragma unroll
    for (int o = 0; o < C2; o++) { a[o] = 0.f; r[o] = 0.f; }

    for (int k = 0; k < NCH; k++) {
        uint32_t bits[NTAP2];
#pragma unroll
        for (int c = 0; c < C1; c++)
#pragma unroll
            for (int dy = 0; dy < 3; dy++)
#pragma unroll
                for (int dx = 0; dx < 3; dx++) {
                    int hh = h + dy - 1, ww = w + dx - 1;
                    uint32_t v = 0;
                    if (hh >= 0 && hh < HH && ww >= 0 && ww < WW)
                        v = g_s1[(((b * NCH + k) * C1 + c) * HH + hh) * WW + ww];
                    bits[(c * 3 + dy) * 3 + dx] = v;
                }

        uint32_t sb[C2];
#pragma unroll
        for (int o = 0; o < C2; o++) sb[o] = 0u;

#pragma unroll 1
        for (int jg = 0; jg < 4; jg++) {
            float4 sl[8], sh[8];
#pragma unroll
            for (int jj = 0; jj < 8; jj++) {
                sl[jj] = make_float4(0.f, 0.f, 0.f, 0.f);
                sh[jj] = make_float4(0.f, 0.f, 0.f, 0.f);
            }
#pragma unroll 1
            for (int c = 0; c < C1; c++) {
                unsigned long long tx = t8x8(bits + c * 9, jg);
#pragma unroll
                for (int jj = 0; jj < 8; jj++) {
                    int m = (int)(tx >> (8 * jj)) & 0xFF;
                    const float4* e = &lutv[(size_t)((c << 8) | m) << 1];
                    addf4(sl[jj], e[0]);
                    addf4(sh[jj], e[1]);
                }
                float4 e0 = exv[c * 2], e1 = exv[c * 2 + 1];
                uint32_t b8 = (bits[c * 9 + 8] >> (jg * 8)) & 0xFF;
#pragma unroll
                for (int jj = 0; jj < 8; jj++)
                    if ((b8 >> jj) & 1u) { addf4(sl[jj], e0); addf4(sh[jj], e1); }
            }
#pragma unroll
            for (int jj = 0; jj < 8; jj++) {
                int j = jg * 8 + jj;
                float su[8] = {sl[jj].x, sl[jj].y, sl[jj].z, sl[jj].w,
                               sh[jj].x, sh[jj].y, sh[jj].z, sh[jj].w};
#pragma unroll
                for (int o = 0; o < C2; o++) {
                    a[o] = D2 * a[o] + su[o];
                    float v = a[o] + r[o];
                    bool hd = v >= 50.0f;
                    sb[o] |= hd ? (1u << j) : 0u;
                    r[o] = D2 * r[o] - (hd ? 50.0f : 0.0f);
                }
            }
        }
#pragma unroll
        for (int o = 0; o < C2; o++)
            g_s2[(((b * NCH + k) * C2 + o) * HH + h) * WW + w] = sb[o];
    }
}

// =====================================================================
// K3: layer 3 (reverted to proven R5 version, 84.8us).
//   u3 = IIR_4(convT2x2(s2bits)) + IIR_1(bilinear2x(xbits)); spike(th=100, dref=D3)
// =====================================================================
__global__ void __launch_bounds__(128) k_layer3(const float* __restrict__ wup,
                                                float* __restrict__ out) {
    __shared__ float swu[64];
    if (threadIdx.x < 64) swu[threadIdx.x] = wup[threadIdx.x];
    __syncthreads();

    int tid = blockIdx.x * blockDim.x + threadIdx.x;
    int wo = tid & 127; int t1 = tid >> 7;
    int ho = t1 & 127;  int b  = t1 >> 7;
    int hi = ho >> 1, wi = wo >> 1;
    int pa = ho & 1,  pb = wo & 1;

    int r0, r1, c0, c1; float wr0, wr1, wc0, wc1;
    if (!pa) { r0 = (hi > 0) ? hi - 1 : 0;  r1 = hi; wr0 = 0.25f; wr1 = 0.75f; }
    else     { r0 = hi; r1 = (hi < 63) ? hi + 1 : 63; wr0 = 0.75f; wr1 = 0.25f; }
    if (!pb) { c0 = (wi > 0) ? wi - 1 : 0;  c1 = wi; wc0 = 0.25f; wc1 = 0.75f; }
    else     { c0 = wi; c1 = (wi < 63) ? wi + 1 : 63; wc0 = 0.75f; wc1 = 0.25f; }
    float tw00 = wr0 * wc0, tw01 = wr0 * wc1, tw10 = wr1 * wc0, tw11 = wr1 * wc1;

    int lane = threadIdx.x & 31;
    int wo0  = wo & ~31;

    float a[2], p[2], rr[2];
#pragma unroll
    for (int o = 0; o < 2; o++) { a[o] = 0.f; p[o] = 0.f; rr[o] = 0.f; }

    for (int k = 0; k < NCH; k++) {
        uint32_t s2b[C2];
#pragma unroll
        for (int c = 0; c < C2; c++)
            s2b[c] = g_s2[(((b * NCH + k) * C2 + c) * HH + hi) * WW + wi];
        uint32_t xb00[2], xb01[2], xb10[2], xb11[2];
#pragma unroll
        for (int c = 0; c < 2; c++) {
            const uint32_t* xp = g_xbits + (size_t)(((b * NCH + k) * CIN) + c) * HH * WW;
            xb00[c] = xp[r0 * WW + c0]; xb01[c] = xp[r0 * WW + c1];
            xb10[c] = xp[r1 * WW + c0]; xb11[c] = xp[r1 * WW + c1];
        }
#pragma unroll 1
        for (int o = 0; o < 2; o++) {
            float sA[32], sX[32];
#pragma unroll
            for (int j = 0; j < 32; j++) { sA[j] = 0.f; sX[j] = 0.f; }
#pragma unroll
            for (int c = 0; c < C2; c++) {
                float wv = swu[((o * 8 + c) * 2 + (1 - pa)) * 2 + (1 - pb)];
                uint32_t bw = s2b[c];
#pragma unroll
                for (int j = 0; j < 32; j++)
                    if (bw & (1u << j)) sA[j] += wv;
            }
            {
                uint32_t bw = xb00[o];
#pragma unroll
                for (int j = 0; j < 32; j++) if (bw & (1u << j)) sX[j] += tw00;
            }
            {
                uint32_t bw = xb01[o];
#pragma unroll
                for (int j = 0; j < 32; j++) if (bw & (1u << j)) sX[j] += tw01;
            }
            {
                uint32_t bw = xb10[o];
#pragma unroll
                for (int j = 0; j < 32; j++) if (bw & (1u << j)) sX[j] += tw10;
            }
            {
                uint32_t bw = xb11[o];
#pragma unroll
                for (int j = 0; j < 32; j++) if (bw & (1u << j)) sX[j] += tw11;
            }
            uint32_t sb = 0;
            float av = a[o], pv = p[o], rv = rr[o];
#pragma unroll
            for (int j = 0; j < 32; j++) {
                av = D3 * av + sA[j];
                pv = D1 * pv + sX[j];
                float v = av + pv + rv;
                bool hd = v >= 100.0f;
                sb |= hd ? (1u << j) : 0u;
                rv = D3 * rv - (hd ? 100.0f : 0.0f);
            }
            a[o] = av; p[o] = pv; rr[o] = rv;

            size_t rowbase = ((size_t)((b * 2 + o) * 128 + ho) * 128 + wo0) * TT;
            int t = k * 32 + lane;
#pragma unroll
            for (int pl = 0; pl < 32; pl++) {
                uint32_t wv = __shfl_sync(0xffffffffu, sb, pl);
                if (t < TT)
                    out[rowbase + (size_t)pl * TT + t] = ((wv >> lane) & 1u) ? 1.0f : 0.0f;
            }
        }
    }
}

// =====================================================================
extern "C" void kernel_launch(void* const* d_in, const int* in_sizes, int n_in,
                              void* d_out, int out_size) {
    const float* x   = (const float*)d_in[0];
    const float* w1  = (const float*)d_in[1];
    const float* w2  = (const float*)d_in[2];
    const float* wup = (const float*)d_in[3];
    float* out = (float*)d_out;

    int smem1 = SMEM1_FLOATS * 4;   // 49,216 B
    int smem2 = SMEM2_FLOATS * 4;   // 65,792 B
    cudaFuncSetAttribute(k_layer1, cudaFuncAttributeMaxDynamicSharedMemorySize, smem1);
    cudaFuncSetAttribute(k_layer2, cudaFuncAttributeMaxDynamicSharedMemorySize, smem2);

    int n0 = BATCH * CIN * HH * WW * NCH;
    k_binarize<<<(n0 + 255) / 256, 256>>>(x);
    k_layer1<<<(BATCH * HH * WW) / 128, 128, smem1>>>(w1);      // 256 blocks
    k_layer2<<<(BATCH * HH * WW) / 128, 128, smem2>>>(w2);      // 256 blocks
    k_layer3<<<(BATCH * 128 * 128) / 128, 128>>>(wup, out);     // 1024 blocks
}